// round 4
// baseline (speedup 1.0000x reference)
#include <cuda_runtime.h>
#include <math.h>

// Problem constants
#define BB   8
#define CC_  256
#define HH   96
#define WW   128
#define RR   4
#define DD   9                 // 2R+1
#define HWSZ (HH*WW)           // 12288
#define CHW  (CC_*HWSZ)        // 3145728

// Correlation tiling
#define XT   32                // x pixels per block
#define YT   8                 // y pixels per block
#define KC   8                 // channels per smem chunk
#define FQH  (YT + 2*RR)       // 16
#define FQW  (XT + 2*RR)       // 40
#define FQS  52                // swizzled fq row stride (floats), == 4 mod 8
#define FRS  36                // swizzled fr row stride (floats), == 4 mod 8
#define NTHR 288               // 4 xg * 8 yr * 9 dy

// phys(j) = 9*(j>>3) + (j&7): groups of 8 floats at stride 9 -> with row
// strides ==4 (mod 8), bank = S*yr + 9*xg + imm is a bijection over the 32
// lanes (8 yr x 4 xg) -> every scalar LDS is one conflict-free wavefront.

__device__ float g_invr[BB*HWSZ];   // holds invnorm(fr) / 256
__device__ float g_invq[BB*HWSZ];   // holds invnorm(fq)

// ---------------------------------------------------------------------------
// Kernel 1: per-pixel inverse L2 norms (1/256 folded into fr side)
// ---------------------------------------------------------------------------
__global__ __launch_bounds__(256) void norm_kernel(const float* __restrict__ fr,
                                                   const float* __restrict__ fq)
{
    int p = blockIdx.x * 256 + threadIdx.x;
    if (p >= BB*HWSZ) return;
    int b  = p / HWSZ;
    int yx = p - b * HWSZ;
    const float* pr = fr + (size_t)b * CHW + yx;
    const float* pq = fq + (size_t)b * CHW + yx;
    float sr = 0.f, sq = 0.f;
#pragma unroll 8
    for (int c = 0; c < CC_; c++) {
        float a = pr[(size_t)c * HWSZ];
        float d = pq[(size_t)c * HWSZ];
        sr = fmaf(a, a, sr);
        sq = fmaf(d, d, sq);
    }
    g_invr[p] = (1.0f/256.0f) / fmaxf(sqrtf(sr), 1e-12f);
    g_invq[p] = 1.0f / fmaxf(sqrtf(sq), 1e-12f);
}

// ---------------------------------------------------------------------------
// Kernel 2: banded correlation. Block tile YT x XT, all 81 displacements.
// Thread (xg,yr,dy): 8 contiguous x-pixels, one y row, one dy; 9 dx in regs.
// ---------------------------------------------------------------------------
__global__ __launch_bounds__(NTHR, 2) void corr_kernel(const float* __restrict__ fr,
                                                       const float* __restrict__ fq,
                                                       float* __restrict__ out)
{
    __shared__ float s_fq[KC * FQH * FQS];   // 26624 B (swizzled)
    __shared__ float s_fr[KC * YT  * FRS];   //  9216 B (swizzled)
    __shared__ float s_iq[FQH * FQW];        //  2560 B (plain)

    const int tid = threadIdx.x;
    const int xg  = tid & 3;           // 0..3 -> pixels xg*8 .. xg*8+7
    const int yr  = (tid >> 2) & 7;    // 0..7
    const int dy  = tid >> 5;          // 0..8 (one dy per warp)

    const int x0 = blockIdx.x * XT;
    const int y0 = blockIdx.y * YT;
    const int b  = blockIdx.z;

    // Stage invq halo tile once (zero outside image = zero padding).
    for (int e = tid; e < FQH * FQW; e += NTHR) {
        int ry = e / FQW;
        int j  = e - ry * FQW;
        int gy = y0 + ry - RR;
        int gx = x0 + j  - RR;
        float v = 0.f;
        if ((unsigned)gy < (unsigned)HH && (unsigned)gx < (unsigned)WW)
            v = g_invq[b * HWSZ + gy * WW + gx];
        s_iq[e] = v;
    }

    float acc[DD][8];
#pragma unroll
    for (int d = 0; d < DD; d++)
#pragma unroll
        for (int i = 0; i < 8; i++) acc[d][i] = 0.f;

    const float* frb = fr + (size_t)b * CHW + y0 * WW + x0;
    const float* fqb = fq + (size_t)b * CHW;

    // Per-thread smem bases (element offsets, channel 0)
    const float* abase = s_fr + yr * FRS + 9 * xg;
    const float* qbase = s_fq + (yr + dy) * FQS + 9 * xg;

    for (int c0 = 0; c0 < CC_; c0 += KC) {
        __syncthreads();

        // ---- stage fq chunk: KC*FQH*10 float4 groups = 1280
#pragma unroll
        for (int k = 0; k < 5; k++) {
            int g = k * NTHR + tid;
            if (g < KC * FQH * (FQW/4)) {
                int q4 = g % (FQW/4);                 // 0..9
                int r2 = g / (FQW/4);
                int ry = r2 & (FQH - 1);              // 0..15
                int cc = r2 >> 4;
                int gy = y0 + ry - RR;
                int gx = x0 + q4 * 4 - RR;
                float4 v = make_float4(0.f, 0.f, 0.f, 0.f);
                if ((unsigned)gy < (unsigned)HH && (unsigned)gx < (unsigned)(WW - 3))
                    v = *reinterpret_cast<const float4*>(
                        fqb + (size_t)(c0 + cc) * HWSZ + gy * WW + gx);
                float* dst = s_fq + (cc * FQH + ry) * FQS + (q4 >> 1) * 9 + (q4 & 1) * 4;
                dst[0] = v.x; dst[1] = v.y; dst[2] = v.z; dst[3] = v.w;
            }
        }

        // ---- stage fr chunk: KC*YT*8 float4 groups = 512
#pragma unroll
        for (int k = 0; k < 2; k++) {
            int g = k * NTHR + tid;
            if (g < KC * YT * (XT/4)) {
                int q4 = g & 7;
                int ry = (g >> 3) & 7;
                int cc = g >> 6;
                float4 v = *reinterpret_cast<const float4*>(
                    frb + (size_t)(c0 + cc) * HWSZ + ry * WW + q4 * 4);
                float* dst = s_fr + (cc * YT + ry) * FRS + (q4 >> 1) * 9 + (q4 & 1) * 4;
                dst[0] = v.x; dst[1] = v.y; dst[2] = v.z; dst[3] = v.w;
            }
        }

        __syncthreads();

        // ---- compute: per channel, 24 conflict-free scalar LDS feed 72 FFMA
#pragma unroll
        for (int cc = 0; cc < KC; cc++) {
            const float* ap = abase + cc * (YT * FRS);
            const float* qp = qbase + cc * (FQH * FQS);

            float a[8], q[16];
#pragma unroll
            for (int i = 0; i < 8; i++) a[i] = ap[i];
#pragma unroll
            for (int i = 0; i < 8; i++) q[i] = qp[i];
#pragma unroll
            for (int i = 0; i < 8; i++) q[8 + i] = qp[9 + i];   // next 8-group at +9

#pragma unroll
            for (int dx = 0; dx < DD; dx++)
#pragma unroll
                for (int i = 0; i < 8; i++)
                    acc[dx][i] = fmaf(a[i], q[i + dx], acc[dx][i]);
        }
    }

    // ---- epilogue: scale by (invr/256) * invq and store
    const int gy = y0 + yr;

    float iq[16];
    {
        const float* iqp = s_iq + (yr + dy) * FQW + xg * 8;
#pragma unroll
        for (int k = 0; k < 16; k++) iq[k] = iqp[k];
    }
    float ir[8];
    {
        const float* irp = g_invr + b * HWSZ + gy * WW + x0 + xg * 8;
#pragma unroll
        for (int i = 0; i < 8; i++) ir[i] = irp[i];
    }

#pragma unroll
    for (int dx = 0; dx < DD; dx++) {
        float o[8];
#pragma unroll
        for (int i = 0; i < 8; i++)
            o[i] = acc[dx][i] * ir[i] * iq[i + dx];
        float* op = out + ((size_t)(b * (DD*DD) + dy * DD + dx) * HH + gy) * WW
                        + x0 + xg * 8;
        *reinterpret_cast<float4*>(op + 0) = make_float4(o[0], o[1], o[2], o[3]);
        *reinterpret_cast<float4*>(op + 4) = make_float4(o[4], o[5], o[6], o[7]);
    }
}

// ---------------------------------------------------------------------------
extern "C" void kernel_launch(void* const* d_in, const int* in_sizes, int n_in,
                              void* d_out, int out_size)
{
    const float* fr = (const float*)d_in[0];
    const float* fq = (const float*)d_in[1];
    float* out = (float*)d_out;

    norm_kernel<<<(BB * HWSZ + 255) / 256, 256>>>(fr, fq);

    dim3 grid(WW / XT, HH / YT, BB);   // (4, 12, 8) = 384 blocks
    corr_kernel<<<grid, NTHR>>>(fr, fq, out);
}

// round 5
// speedup vs baseline: 1.4983x; 1.4983x over previous
#include <cuda_runtime.h>
#include <math.h>

// Problem constants
#define BB   8
#define CC_  256
#define HH   96
#define WW   128
#define RR   4
#define DD   9                 // 2R+1
#define HWSZ (HH*WW)           // 12288
#define CHW  (CC_*HWSZ)        // 3145728

// Tiling (R2 shape: proven 215us compute loop)
#define XT   64
#define YT   4
#define KC   8
#define FQH  (YT + 2*RR)       // 12
#define FQW  (XT + 2*RR)       // 72
#define NTHR 576               // 16 xg * 4 yr * 9 dy
#define NCHUNK (CC_/KC)        // 32
#define QG   3                 // fq float4 groups per thread: 8*12*18/576

// ---------------------------------------------------------------------------
// Fused kernel: banded correlation + in-block norm computation.
// Pipeline: prefetch chunk k+1 from gmem into regs while computing chunk k.
// Norms: staging threads square-accumulate what they store; combined via
// smem atomicAdd once at the end, converted to inverse norms in place.
// ---------------------------------------------------------------------------
__global__ __launch_bounds__(NTHR, 1) void corr_kernel(const float* __restrict__ fr,
                                                       const float* __restrict__ fq,
                                                       float* __restrict__ out)
{
    __shared__ float s_fq[KC * FQH * FQW];   // 27648 B
    __shared__ float s_fr[KC * YT * XT];     //  8192 B
    __shared__ float s_sq[FQH * FQW];        //  3456 B  (sum fq^2 -> invq)
    __shared__ float s_sr[YT * XT];          //  1024 B  (sum fr^2 -> invr/256)

    const int tid = threadIdx.x;
    const int xg  = tid & 15;          // 0..15 -> pixels xg*4..xg*4+3
    const int yr  = (tid >> 4) & 3;    // 0..3
    const int dy  = tid / 64;          // 0..8 (dy per warp-pair)

    const int x0 = blockIdx.x * XT;
    const int y0 = blockIdx.y * YT;
    const int b  = blockIdx.z;

    // zero the sum arrays
    for (int e = tid; e < FQH * FQW; e += NTHR) s_sq[e] = 0.f;
    if (tid < YT * XT) s_sr[tid] = 0.f;

    // ---- precompute staging descriptors (fixed per thread across chunks)
    const float* qsrc[QG];
    int qdst[QG], qslot[QG];
#pragma unroll
    for (int k = 0; k < QG; k++) {
        int g  = tid + k * NTHR;           // 0..1727
        int q4 = g % (FQW / 4);            // 0..17
        int r2 = g / (FQW / 4);
        int ry = r2 % FQH;                 // 0..11
        int cc = r2 / FQH;                 // 0..7
        int gy = y0 + ry - RR;
        int gx = x0 + q4 * 4 - RR;
        bool ok = ((unsigned)gy < (unsigned)HH) && ((unsigned)gx < (unsigned)(WW - 3));
        qsrc[k]  = ok ? fq + (size_t)b * CHW + (size_t)cc * HWSZ + gy * WW + gx : nullptr;
        qdst[k]  = (cc * FQH + ry) * FQW + q4 * 4;
        qslot[k] = ry * FQW + q4 * 4;
    }
    const float* rsrc = nullptr;
    int rdst = 0, rslot = 0;
    if (tid < 512) {
        int cc  = tid >> 6;
        int rem = tid & 63;
        int yy  = rem >> 4;
        int xq  = rem & 15;
        rsrc  = fr + (size_t)b * CHW + (size_t)cc * HWSZ + (y0 + yy) * WW + x0 + xq * 4;
        rdst  = (cc * YT + yy) * XT + xq * 4;
        rslot = yy * XT + xq * 4;
    }

    // ---- prefetch chunk 0
    float4 vq[QG], vr = make_float4(0.f, 0.f, 0.f, 0.f);
#pragma unroll
    for (int k = 0; k < QG; k++)
        vq[k] = qsrc[k] ? *reinterpret_cast<const float4*>(qsrc[k])
                        : make_float4(0.f, 0.f, 0.f, 0.f);
    if (rsrc) vr = *reinterpret_cast<const float4*>(rsrc);

    float acc[DD][4];
#pragma unroll
    for (int d = 0; d < DD; d++)
#pragma unroll
        for (int i = 0; i < 4; i++) acc[d][i] = 0.f;

    float4 sq[QG];
#pragma unroll
    for (int k = 0; k < QG; k++) sq[k] = make_float4(0.f, 0.f, 0.f, 0.f);
    float4 sr = make_float4(0.f, 0.f, 0.f, 0.f);

    const float* abase = s_fr + yr * XT + xg * 4;
    const float* qbase = s_fq + (yr + dy) * FQW + xg * 4;

    for (int ch = 0; ch < NCHUNK; ch++) {
        __syncthreads();   // previous compute done; smem free for restaging

        // ---- STS from prefetch regs + square-accumulate for norms
#pragma unroll
        for (int k = 0; k < QG; k++) {
            float4 v = vq[k];
            float* d = s_fq + qdst[k];
            d[0] = v.x; d[1] = v.y; d[2] = v.z; d[3] = v.w;
            sq[k].x = fmaf(v.x, v.x, sq[k].x);
            sq[k].y = fmaf(v.y, v.y, sq[k].y);
            sq[k].z = fmaf(v.z, v.z, sq[k].z);
            sq[k].w = fmaf(v.w, v.w, sq[k].w);
        }
        if (rsrc) {
            float* d = s_fr + rdst;
            d[0] = vr.x; d[1] = vr.y; d[2] = vr.z; d[3] = vr.w;
            sr.x = fmaf(vr.x, vr.x, sr.x);
            sr.y = fmaf(vr.y, vr.y, sr.y);
            sr.z = fmaf(vr.z, vr.z, sr.z);
            sr.w = fmaf(vr.w, vr.w, sr.w);
        }

        __syncthreads();   // staged data visible

        // ---- prefetch next chunk (latency hidden by compute below)
        if (ch + 1 < NCHUNK) {
            size_t off = (size_t)(ch + 1) * KC * HWSZ;
#pragma unroll
            for (int k = 0; k < QG; k++)
                vq[k] = qsrc[k] ? *reinterpret_cast<const float4*>(qsrc[k] + off)
                                : make_float4(0.f, 0.f, 0.f, 0.f);
            if (rsrc) vr = *reinterpret_cast<const float4*>(rsrc + off);
        }

        // ---- compute: per channel, 4 LDS.128 feed 36 FFMA
#pragma unroll
        for (int cc = 0; cc < KC; cc++) {
            float4 a4 = *reinterpret_cast<const float4*>(abase + cc * (YT * XT));
            float a[4] = {a4.x, a4.y, a4.z, a4.w};

            float q[12];
            {
                const float* qp = qbase + cc * (FQH * FQW);
                float4 q0 = *reinterpret_cast<const float4*>(qp + 0);
                float4 q1 = *reinterpret_cast<const float4*>(qp + 4);
                float4 q2 = *reinterpret_cast<const float4*>(qp + 8);
                q[0]=q0.x; q[1]=q0.y; q[2]=q0.z; q[3]=q0.w;
                q[4]=q1.x; q[5]=q1.y; q[6]=q1.z; q[7]=q1.w;
                q[8]=q2.x; q[9]=q2.y; q[10]=q2.z; q[11]=q2.w;
            }

#pragma unroll
            for (int dx = 0; dx < DD; dx++)
#pragma unroll
                for (int i = 0; i < 4; i++)
                    acc[dx][i] = fmaf(a[i], q[i + dx], acc[dx][i]);
        }
    }

    // ---- combine norm partials (8 contributors per slot)
#pragma unroll
    for (int k = 0; k < QG; k++) {
        atomicAdd(&s_sq[qslot[k] + 0], sq[k].x);
        atomicAdd(&s_sq[qslot[k] + 1], sq[k].y);
        atomicAdd(&s_sq[qslot[k] + 2], sq[k].z);
        atomicAdd(&s_sq[qslot[k] + 3], sq[k].w);
    }
    if (rsrc) {
        atomicAdd(&s_sr[rslot + 0], sr.x);
        atomicAdd(&s_sr[rslot + 1], sr.y);
        atomicAdd(&s_sr[rslot + 2], sr.z);
        atomicAdd(&s_sr[rslot + 3], sr.w);
    }
    __syncthreads();

    // ---- convert sums to inverse norms in place
    for (int e = tid; e < FQH * FQW; e += NTHR)
        s_sq[e] = 1.0f / fmaxf(sqrtf(s_sq[e]), 1e-12f);
    if (tid < YT * XT)
        s_sr[tid] = (1.0f / 256.0f) / fmaxf(sqrtf(s_sr[tid]), 1e-12f);
    __syncthreads();

    // ---- epilogue: scale by (invr/256) * invq and store
    const int gy = y0 + yr;
    float ir[4];
#pragma unroll
    for (int i = 0; i < 4; i++) ir[i] = s_sr[yr * XT + xg * 4 + i];

    float iq[12];
    {
        const float* iqp = s_sq + (yr + dy) * FQW + xg * 4;
#pragma unroll
        for (int i = 0; i < 12; i++) iq[i] = iqp[i];
    }

#pragma unroll
    for (int dx = 0; dx < DD; dx++) {
        float4 o;
        o.x = acc[dx][0] * ir[0] * iq[0 + dx];
        o.y = acc[dx][1] * ir[1] * iq[1 + dx];
        o.z = acc[dx][2] * ir[2] * iq[2 + dx];
        o.w = acc[dx][3] * ir[3] * iq[3 + dx];
        float* op = out + ((size_t)(b * (DD * DD) + dy * DD + dx) * HH + gy) * WW
                        + x0 + xg * 4;
        *reinterpret_cast<float4*>(op) = o;
    }
}

// ---------------------------------------------------------------------------
extern "C" void kernel_launch(void* const* d_in, const int* in_sizes, int n_in,
                              void* d_out, int out_size)
{
    const float* fr = (const float*)d_in[0];
    const float* fq = (const float*)d_in[1];
    float* out = (float*)d_out;

    dim3 grid(WW / XT, HH / YT, BB);   // (2, 24, 8) = 384 blocks
    corr_kernel<<<grid, NTHR>>>(fr, fq, out);
}

// round 6
// speedup vs baseline: 1.7361x; 1.1588x over previous
#include <cuda_runtime.h>
#include <math.h>

// Problem constants
#define BB   8
#define CC_  256
#define HH   96
#define WW   128
#define RR   4
#define DD   9                 // 2R+1
#define HWSZ (HH*WW)           // 12288
#define CHW  (CC_*HWSZ)        // 3145728

// Tiling
#define XT   64
#define YT   4
#define KC   8
#define FQH  (YT + 2*RR)       // 12
#define FQW  (XT + 2*RR)       // 72
#define NTHR 576               // 16 xg * 4 yr * 9 dy
#define NCHUNK (CC_/KC)        // 32
#define QG   3                 // fq float4 groups per thread

#define FQBUF (KC*FQH*FQW)     // 6912 floats per fq buffer
#define FRBUF (KC*YT*XT)       // 2048 floats per fr buffer
#define SMEM_FLOATS (2*FQBUF + 2*FRBUF + FQH*FQW + YT*XT)   // 19040
#define SMEM_BYTES  (SMEM_FLOATS*4)                          // 76160

// Packed fp32x2 helpers (sm_103a)
#define PACK2(d, lo, hi) asm("mov.b64 %0, {%1, %2};" : "=l"(d) : "f"(lo), "f"(hi))
#define FMA2(acc, a, b)  asm("fma.rn.f32x2 %0, %1, %2, %0;" : "+l"(acc) : "l"(a), "l"(b))
#define UNPK2(lo, hi, s) asm("mov.b64 {%0, %1}, %2;" : "=f"(lo), "=f"(hi) : "l"(s))

// ---------------------------------------------------------------------------
__device__ __forceinline__ void stage_chunk(
    float* fq_buf, float* fr_buf,
    const float4* vq, float4 vr,
    const int* qdst, int rdst, bool has_r,
    float4* sq, float4& sr)
{
#pragma unroll
    for (int k = 0; k < QG; k++) {
        float4 v = vq[k];
        float* d = fq_buf + qdst[k];
        d[0] = v.x; d[1] = v.y; d[2] = v.z; d[3] = v.w;
        sq[k].x = fmaf(v.x, v.x, sq[k].x);
        sq[k].y = fmaf(v.y, v.y, sq[k].y);
        sq[k].z = fmaf(v.z, v.z, sq[k].z);
        sq[k].w = fmaf(v.w, v.w, sq[k].w);
    }
    if (has_r) {
        float* d = fr_buf + rdst;
        d[0] = vr.x; d[1] = vr.y; d[2] = vr.z; d[3] = vr.w;
        sr.x = fmaf(vr.x, vr.x, sr.x);
        sr.y = fmaf(vr.y, vr.y, sr.y);
        sr.z = fmaf(vr.z, vr.z, sr.z);
        sr.w = fmaf(vr.w, vr.w, sr.w);
    }
}

// ---------------------------------------------------------------------------
// Fused correlation + norms. Double-buffered smem (1 barrier/chunk),
// register prefetch of next chunk, packed f32x2 FMA inner loop.
// ---------------------------------------------------------------------------
__global__ __launch_bounds__(NTHR, 1) void corr_kernel(const float* __restrict__ fr,
                                                       const float* __restrict__ fq,
                                                       float* __restrict__ out)
{
    extern __shared__ float smem[];
    float* s_fq = smem;                         // 2 * 6912
    float* s_fr = smem + 2 * FQBUF;             // 2 * 2048
    float* s_sq = smem + 2 * FQBUF + 2 * FRBUF; // 864
    float* s_sr = s_sq + FQH * FQW;             // 256

    const int tid = threadIdx.x;
    const int xg  = tid & 15;
    const int yr  = (tid >> 4) & 3;
    const int dy  = tid / 64;

    const int x0 = blockIdx.x * XT;
    const int y0 = blockIdx.y * YT;
    const int b  = blockIdx.z;

    // zero norm-sum arrays
    for (int e = tid; e < FQH * FQW; e += NTHR) s_sq[e] = 0.f;
    if (tid < YT * XT) s_sr[tid] = 0.f;

    // ---- staging descriptors (fixed per thread)
    const float* qsrc[QG];
    int qdst[QG], qslot[QG];
#pragma unroll
    for (int k = 0; k < QG; k++) {
        int g  = tid + k * NTHR;
        int q4 = g % (FQW / 4);
        int r2 = g / (FQW / 4);
        int ry = r2 % FQH;
        int cc = r2 / FQH;
        int gy = y0 + ry - RR;
        int gx = x0 + q4 * 4 - RR;
        bool ok = ((unsigned)gy < (unsigned)HH) && ((unsigned)gx < (unsigned)(WW - 3));
        qsrc[k]  = ok ? fq + (size_t)b * CHW + (size_t)cc * HWSZ + gy * WW + gx : nullptr;
        qdst[k]  = (cc * FQH + ry) * FQW + q4 * 4;
        qslot[k] = ry * FQW + q4 * 4;
    }
    const float* rsrc = nullptr;
    int rdst = 0, rslot = 0;
    if (tid < 512) {
        int cc  = tid >> 6;
        int rem = tid & 63;
        int yy  = rem >> 4;
        int xq  = rem & 15;
        rsrc  = fr + (size_t)b * CHW + (size_t)cc * HWSZ + (y0 + yy) * WW + x0 + xq * 4;
        rdst  = (cc * YT + yy) * XT + xq * 4;
        rslot = yy * XT + xq * 4;
    }

    // norm partial sums
    float4 sq[QG];
#pragma unroll
    for (int k = 0; k < QG; k++) sq[k] = make_float4(0.f, 0.f, 0.f, 0.f);
    float4 sr = make_float4(0.f, 0.f, 0.f, 0.f);

    // packed accumulators: acc2[dx][0] = pixels 0,1 ; acc2[dx][1] = pixels 2,3
    unsigned long long acc2[DD][2];
#pragma unroll
    for (int d = 0; d < DD; d++) { acc2[d][0] = 0ull; acc2[d][1] = 0ull; }

    // ---- prefetch + stage chunk 0 into buffer 0
    float4 vq[QG], vr = make_float4(0.f, 0.f, 0.f, 0.f);
#pragma unroll
    for (int k = 0; k < QG; k++)
        vq[k] = qsrc[k] ? *reinterpret_cast<const float4*>(qsrc[k])
                        : make_float4(0.f, 0.f, 0.f, 0.f);
    if (rsrc) vr = *reinterpret_cast<const float4*>(rsrc);
    stage_chunk(s_fq, s_fr, vq, vr, qdst, rdst, rsrc != nullptr, sq, sr);
    __syncthreads();

    const int qoff = (yr + dy) * FQW + xg * 4;
    const int aoff = yr * XT + xg * 4;

    for (int ch = 0; ch < NCHUNK; ch++) {
        const int buf  = ch & 1;
        const int nbuf = buf ^ 1;

        // ---- prefetch next chunk (latency hidden by compute)
        if (ch + 1 < NCHUNK) {
            size_t off = (size_t)(ch + 1) * KC * HWSZ;
#pragma unroll
            for (int k = 0; k < QG; k++)
                vq[k] = qsrc[k] ? *reinterpret_cast<const float4*>(qsrc[k] + off)
                                : make_float4(0.f, 0.f, 0.f, 0.f);
            if (rsrc) vr = *reinterpret_cast<const float4*>(rsrc + off);
        }

        const float* abase = s_fr + buf * FRBUF + aoff;
        const float* qbase = s_fq + buf * FQBUF + qoff;

        // ---- compute: per channel 4 LDS.128 -> 13 packs + 18 FFMA2
#pragma unroll
        for (int cc = 0; cc < KC; cc++) {
            float4 a4 = *reinterpret_cast<const float4*>(abase + cc * (YT * XT));
            const float* qp_ = qbase + cc * (FQH * FQW);
            float4 q0 = *reinterpret_cast<const float4*>(qp_ + 0);
            float4 q1 = *reinterpret_cast<const float4*>(qp_ + 4);
            float4 q2 = *reinterpret_cast<const float4*>(qp_ + 8);
            float q[12] = {q0.x, q0.y, q0.z, q0.w,
                           q1.x, q1.y, q1.z, q1.w,
                           q2.x, q2.y, q2.z, q2.w};

            unsigned long long a01, a23, qp2[11];
            PACK2(a01, a4.x, a4.y);
            PACK2(a23, a4.z, a4.w);
#pragma unroll
            for (int k = 0; k < 11; k++) PACK2(qp2[k], q[k], q[k + 1]);

#pragma unroll
            for (int dx = 0; dx < DD; dx++) {
                FMA2(acc2[dx][0], a01, qp2[dx]);
                FMA2(acc2[dx][1], a23, qp2[dx + 2]);
            }
        }

        // ---- stage next chunk into the other buffer (overlapped, pre-barrier)
        if (ch + 1 < NCHUNK)
            stage_chunk(s_fq + nbuf * FQBUF, s_fr + nbuf * FRBUF,
                        vq, vr, qdst, rdst, rsrc != nullptr, sq, sr);

        __syncthreads();
    }

    // ---- combine norm partials
#pragma unroll
    for (int k = 0; k < QG; k++) {
        atomicAdd(&s_sq[qslot[k] + 0], sq[k].x);
        atomicAdd(&s_sq[qslot[k] + 1], sq[k].y);
        atomicAdd(&s_sq[qslot[k] + 2], sq[k].z);
        atomicAdd(&s_sq[qslot[k] + 3], sq[k].w);
    }
    if (rsrc) {
        atomicAdd(&s_sr[rslot + 0], sr.x);
        atomicAdd(&s_sr[rslot + 1], sr.y);
        atomicAdd(&s_sr[rslot + 2], sr.z);
        atomicAdd(&s_sr[rslot + 3], sr.w);
    }
    __syncthreads();

    for (int e = tid; e < FQH * FQW; e += NTHR)
        s_sq[e] = 1.0f / fmaxf(sqrtf(s_sq[e]), 1e-12f);
    if (tid < YT * XT)
        s_sr[tid] = (1.0f / 256.0f) / fmaxf(sqrtf(s_sr[tid]), 1e-12f);
    __syncthreads();

    // ---- epilogue
    const int gy = y0 + yr;
    float ir[4];
#pragma unroll
    for (int i = 0; i < 4; i++) ir[i] = s_sr[yr * XT + xg * 4 + i];

    float iq[12];
    {
        const float* iqp = s_sq + (yr + dy) * FQW + xg * 4;
#pragma unroll
        for (int i = 0; i < 12; i++) iq[i] = iqp[i];
    }

#pragma unroll
    for (int dx = 0; dx < DD; dx++) {
        float p0, p1, p2, p3;
        UNPK2(p0, p1, acc2[dx][0]);
        UNPK2(p2, p3, acc2[dx][1]);
        float4 o;
        o.x = p0 * ir[0] * iq[0 + dx];
        o.y = p1 * ir[1] * iq[1 + dx];
        o.z = p2 * ir[2] * iq[2 + dx];
        o.w = p3 * ir[3] * iq[3 + dx];
        float* op = out + ((size_t)(b * (DD * DD) + dy * DD + dx) * HH + gy) * WW
                        + x0 + xg * 4;
        *reinterpret_cast<float4*>(op) = o;
    }
}

// ---------------------------------------------------------------------------
extern "C" void kernel_launch(void* const* d_in, const int* in_sizes, int n_in,
                              void* d_out, int out_size)
{
    const float* fr = (const float*)d_in[0];
    const float* fq = (const float*)d_in[1];
    float* out = (float*)d_out;

    static int attr_set = 0;
    if (!attr_set) {
        cudaFuncSetAttribute((const void*)corr_kernel,
                             cudaFuncAttributeMaxDynamicSharedMemorySize, SMEM_BYTES);
        attr_set = 1;
    }

    dim3 grid(WW / XT, HH / YT, BB);   // (2, 24, 8) = 384 blocks
    corr_kernel<<<grid, NTHR, SMEM_BYTES>>>(fr, fq, out);
}